// round 3
// baseline (speedup 1.0000x reference)
#include <cuda_runtime.h>
#include <cstdint>
#include <math.h>

// ---------------- scratch (static device globals; no allocation) ----------------
#define T_MAX 32768
#define NVAL 122              // 61 landmarks x 2 coords
#define ROWPAD 128            // padded row stride for staging buffer
#define NSEG 512

__device__ float g_raw[(size_t)T_MAX * ROWPAD];  // per-frame 122 values (hand computed, lips raw w/ NaN)
__device__ int   g_keep[T_MAX];
__device__ int   g_kept[T_MAX];                  // compacted kept-frame indices
__device__ float g_lipsum[80];
__device__ int   g_lipcnt[80];
__device__ int   g_S;
__device__ float g_sampled[NSEG * NVAL];

// ---------------- kernel 0: zero accumulators ----------------
__global__ void kInit() {
    int i = threadIdx.x;
    if (i < 80) { g_lipsum[i] = 0.0f; g_lipcnt[i] = 0; }
}

// ---------------- kernel A: per-frame gather + hand transform + keep + lips accum ----------------
// one warp per frame, 32 frames (1024 threads) per block
__global__ __launch_bounds__(1024) void kA(const float* __restrict__ frames,
                                           const int* __restrict__ lips_idx,
                                           int T) {
    __shared__ float s_sum[80];
    __shared__ int   s_cnt[80];
    __shared__ int   s_idx[40];

    int tid = threadIdx.x;
    if (tid < 80) { s_sum[tid] = 0.0f; s_cnt[tid] = 0; }
    if (tid < 40) s_idx[tid] = lips_idx[tid];
    __syncthreads();

    int warp = tid >> 5;
    int lane = tid & 31;
    int t = blockIdx.x * 32 + warp;

    int kp = 0;
    if (t < T) {
        const float* f = frames + (size_t)t * (543 * 3);
        float* row = g_raw + (size_t)t * ROWPAD;

        float h0 = 0.0f, h1 = 0.0f;
        if (lane < 21) {
            float lx = f[(468 + lane) * 3 + 0];
            float ly = f[(468 + lane) * 3 + 1];
            float rx = f[(522 + lane) * 3 + 0];
            float ry = f[(522 + lane) * 3 + 1];
            float a0 = isnan(lx) ? 0.0f : lx;
            float a1 = isnan(ly) ? 0.0f : (1.0f - ly);
            float b0 = isnan(rx) ? 0.0f : (1.0f - rx);
            float b1 = isnan(ry) ? 0.0f : (1.0f - ry);
            h0 = a0 + b0;
            h1 = a1 + b1;
            row[2 * lane]     = h0;
            row[2 * lane + 1] = h1;
        }
        // warp reduction of hand sum -> keep flag
        float s = h0 + h1;
        #pragma unroll
        for (int o = 16; o > 0; o >>= 1) s += __shfl_xor_sync(0xffffffffu, s, o);
        kp = (s != 0.0f) ? 1 : 0;
        if (lane == 0) g_keep[t] = kp;

        // lips gather (raw, keep NaN in staging; accumulate finite sums if kept)
        for (int k = lane; k < 40; k += 32) {
            int l = s_idx[k];
            float x = f[l * 3 + 0];
            float y = f[l * 3 + 1];
            row[42 + 2 * k]     = x;
            row[42 + 2 * k + 1] = y;
            if (kp) {
                if (!isnan(x)) { atomicAdd(&s_sum[2 * k],     x); atomicAdd(&s_cnt[2 * k],     1); }
                if (!isnan(y)) { atomicAdd(&s_sum[2 * k + 1], y); atomicAdd(&s_cnt[2 * k + 1], 1); }
            }
        }
    }
    __syncthreads();
    if (tid < 80) {
        if (s_cnt[tid] != 0) {
            atomicAdd(&g_lipsum[tid], s_sum[tid]);
            atomicAdd(&g_lipcnt[tid], s_cnt[tid]);
        }
    }
}

// ---------------- kernel B: single-block scan of keep flags -> kept list + S ----------------
__global__ __launch_bounds__(1024) void kScan(int T) {
    int tid = threadIdx.x;
    int per = (T + 1023) >> 10;
    int beg = tid * per;
    int end = beg + per; if (end > T) end = T; if (beg > T) beg = T;

    int local = 0;
    for (int i = beg; i < end; i++) local += g_keep[i];

    // block-wide exclusive scan of `local`
    int lane = tid & 31, w = tid >> 5;
    int v = local;
    #pragma unroll
    for (int o = 1; o < 32; o <<= 1) {
        int n = __shfl_up_sync(0xffffffffu, v, o);
        if (lane >= o) v += n;
    }
    __shared__ int ws[32];
    if (lane == 31) ws[w] = v;
    __syncthreads();
    if (w == 0) {
        int x = ws[lane];
        #pragma unroll
        for (int o = 1; o < 32; o <<= 1) {
            int n = __shfl_up_sync(0xffffffffu, x, o);
            if (lane >= o) x += n;
        }
        ws[lane] = x;
    }
    __syncthreads();
    int off = v - local + (w > 0 ? ws[w - 1] : 0);   // exclusive prefix

    for (int i = beg; i < end; i++) {
        if (g_keep[i]) { g_kept[off] = i; off++; }
    }
    if (tid == 1023) g_S = off;   // total kept
}

// ---------------- kernel C: segment means (one block per segment) ----------------
__global__ __launch_bounds__(128) void kC() {
    __shared__ int s_idx[128];   // max segment size for T<=32768 is ~66
    int seg = blockIdx.x;
    int p = threadIdx.x;

    int S = g_S;
    long long D = (S > 0) ? (long long)(S - 1) : 0LL;
    int start = (int)(((long long)seg * D) >> 9);
    int end   = (int)(((long long)(seg + 1) * D) >> 9);
    int n = end - start;

    for (int r = p; r < n; r += 128) s_idx[r] = g_kept[start + r];
    __syncthreads();

    if (p < NVAL) {
        float m = 0.0f;
        bool is_lip = (p >= 42);
        if (is_lip) {
            int c = g_lipcnt[p - 42];
            m = (c > 0) ? (g_lipsum[p - 42] / (float)c) : 0.0f;
        }
        float s0 = 0.0f, s1 = 0.0f, s2 = 0.0f, s3 = 0.0f;
        int r = 0;
        for (; r + 4 <= n; r += 4) {
            float v0 = g_raw[(size_t)s_idx[r + 0] * ROWPAD + p];
            float v1 = g_raw[(size_t)s_idx[r + 1] * ROWPAD + p];
            float v2 = g_raw[(size_t)s_idx[r + 2] * ROWPAD + p];
            float v3 = g_raw[(size_t)s_idx[r + 3] * ROWPAD + p];
            if (is_lip) {
                if (isnan(v0)) v0 = m;
                if (isnan(v1)) v1 = m;
                if (isnan(v2)) v2 = m;
                if (isnan(v3)) v3 = m;
            }
            s0 += v0; s1 += v1; s2 += v2; s3 += v3;
        }
        for (; r < n; r++) {
            float v = g_raw[(size_t)s_idx[r] * ROWPAD + p];
            if (is_lip && isnan(v)) v = m;
            s0 += v;
        }
        float mean = (n > 0) ? ((s0 + s1) + (s2 + s3)) / (float)n : 0.0f;
        g_sampled[seg * NVAL + p] = mean;
    }
}

// ---------------- kernel D: nonzero-row compaction into d_out ----------------
__global__ __launch_bounds__(512) void kD(float* __restrict__ out) {
    __shared__ int flg[NSEG];
    __shared__ int pos[NSEG];
    __shared__ int ws[32];

    int tid = threadIdx.x;   // 512 threads, one row each
    float s = 0.0f;
    for (int c = 0; c < NVAL; c++) s += g_sampled[tid * NVAL + c];
    int f = (s != 0.0f) ? 1 : 0;

    int lane = tid & 31, w = tid >> 5;
    int v = f;
    #pragma unroll
    for (int o = 1; o < 32; o <<= 1) {
        int n = __shfl_up_sync(0xffffffffu, v, o);
        if (lane >= o) v += n;
    }
    if (lane == 31) ws[w] = v;
    __syncthreads();
    if (w == 0) {
        int x = (lane < 16) ? ws[lane] : 0;
        #pragma unroll
        for (int o = 1; o < 32; o <<= 1) {
            int n = __shfl_up_sync(0xffffffffu, x, o);
            if (lane >= o) x += n;
        }
        if (lane < 16) ws[lane] = x;
    }
    __syncthreads();
    int excl = v - f + (w > 0 ? ws[w - 1] : 0);
    flg[tid] = f;
    pos[tid] = excl;
    __syncthreads();

    // coalesced-ish compaction copy
    for (int e = tid; e < NSEG * NVAL; e += 512) {
        int row = e / NVAL;
        int col = e - row * NVAL;
        if (flg[row]) out[pos[row] * NVAL + col] = g_sampled[e];
    }
}

// ---------------- launch ----------------
extern "C" void kernel_launch(void* const* d_in, const int* in_sizes, int n_in,
                              void* d_out, int out_size) {
    const float* frames  = (const float*)d_in[0];
    const int*   lipsidx = (const int*)d_in[1];
    int T = in_sizes[0] / (543 * 3);
    if (T > T_MAX) T = T_MAX;

    kInit<<<1, 128>>>();
    int blocksA = (T + 31) / 32;
    kA<<<blocksA, 1024>>>(frames, lipsidx, T);
    kScan<<<1, 1024>>>(T);
    kC<<<NSEG, 128>>>();
    kD<<<1, 512>>>((float*)d_out);
}

// round 4
// speedup vs baseline: 1.5637x; 1.5637x over previous
#include <cuda_runtime.h>
#include <cstdint>
#include <math.h>

// ---------------- scratch (static device globals; no allocation) ----------------
#define T_MAX 32768
#define NVAL 122              // 61 landmarks x 2 coords
#define ROWPAD 128            // padded row stride for staging buffer
#define NSEG 512
#define NF 4                  // frames per warp in kA

__device__ float g_raw[(size_t)T_MAX * ROWPAD];
__device__ int   g_keep[T_MAX];
__device__ int   g_kept[T_MAX];
__device__ float g_lipsum[80];
__device__ int   g_lipcnt[80];
__device__ int   g_S;
__device__ float g_sampled[NSEG * NVAL];

// ---------------- kernel 0: zero accumulators ----------------
__global__ void kInit() {
    int i = threadIdx.x;
    if (i < 80) { g_lipsum[i] = 0.0f; g_lipcnt[i] = 0; }
}

// ---------------- kernel A: gather + hand transform + keep + lips accum ----------------
// one warp per NF frames; all loads issued before any dependent compute;
// lips sums accumulated in registers, reduced once per block.
__global__ __launch_bounds__(1024) void kA(const float* __restrict__ frames,
                                           const int* __restrict__ lips_idx,
                                           int T) {
    __shared__ int   s_idx[40];
    __shared__ float s_red[32 * 80];
    __shared__ int   s_redc[32 * 80];

    int tid  = threadIdx.x;
    int warp = tid >> 5;
    int lane = tid & 31;

    if (tid < 40) s_idx[tid] = lips_idx[tid];
    __syncthreads();

    int l0 = lane;                         // lips slot 0..31
    int i0 = s_idx[l0];
    int i1 = (lane < 8) ? s_idx[32 + lane] : 0;   // lips slot 32..39

    float ax0 = 0.f, ay0 = 0.f, ax1 = 0.f, ay1 = 0.f;
    int   cx0 = 0,   cy0 = 0,   cx1 = 0,   cy1 = 0;

    int base = (blockIdx.x * 32 + warp) * NF;

    #pragma unroll
    for (int j = 0; j < NF; j++) {
        int t = base + j;
        if (t >= T) break;
        const float* f = frames + (size_t)t * (543 * 3);

        // --- issue ALL loads up front (independent) ---
        float lx = 0.f, ly = 0.f, rx = 0.f, ry = 0.f;
        if (lane < 21) {
            lx = f[(468 + lane) * 3 + 0];
            ly = f[(468 + lane) * 3 + 1];
            rx = f[(522 + lane) * 3 + 0];
            ry = f[(522 + lane) * 3 + 1];
        }
        float x0 = f[i0 * 3 + 0];
        float y0 = f[i0 * 3 + 1];
        float x1 = 0.f, y1 = 0.f;
        if (lane < 8) {
            x1 = f[i1 * 3 + 0];
            y1 = f[i1 * 3 + 1];
        }

        // --- hand transform + keep flag ---
        float h0 = 0.f, h1 = 0.f;
        if (lane < 21) {
            float a0 = isnan(lx) ? 0.f : lx;
            float a1 = isnan(ly) ? 0.f : (1.f - ly);
            float b0 = isnan(rx) ? 0.f : (1.f - rx);
            float b1 = isnan(ry) ? 0.f : (1.f - ry);
            h0 = a0 + b0;
            h1 = a1 + b1;
        }
        float s = h0 + h1;
        #pragma unroll
        for (int o = 16; o > 0; o >>= 1) s += __shfl_xor_sync(0xffffffffu, s, o);
        int kp = (s != 0.0f) ? 1 : 0;

        float* row = g_raw + (size_t)t * ROWPAD;
        if (lane < 21) { row[2 * lane] = h0; row[2 * lane + 1] = h1; }
        if (lane == 0) g_keep[t] = kp;

        // --- lips staging + register accumulation ---
        row[42 + 2 * l0]     = x0;
        row[42 + 2 * l0 + 1] = y0;
        if (lane < 8) {
            row[42 + 2 * (32 + lane)]     = x1;
            row[42 + 2 * (32 + lane) + 1] = y1;
        }
        if (kp) {
            if (!isnan(x0)) { ax0 += x0; cx0++; }
            if (!isnan(y0)) { ay0 += y0; cy0++; }
            if (lane < 8) {
                if (!isnan(x1)) { ax1 += x1; cx1++; }
                if (!isnan(y1)) { ay1 += y1; cy1++; }
            }
        }
    }

    // --- per-warp partials -> shared ---
    s_red [warp * 80 + 2 * l0]     = ax0;
    s_red [warp * 80 + 2 * l0 + 1] = ay0;
    s_redc[warp * 80 + 2 * l0]     = cx0;
    s_redc[warp * 80 + 2 * l0 + 1] = cy0;
    if (lane < 8) {
        s_red [warp * 80 + 64 + 2 * lane]     = ax1;
        s_red [warp * 80 + 64 + 2 * lane + 1] = ay1;
        s_redc[warp * 80 + 64 + 2 * lane]     = cx1;
        s_redc[warp * 80 + 64 + 2 * lane + 1] = cy1;
    }
    __syncthreads();

    if (tid < 80) {
        float sm = 0.f; int cm = 0;
        #pragma unroll
        for (int w = 0; w < 32; w++) {
            sm += s_red [w * 80 + tid];
            cm += s_redc[w * 80 + tid];
        }
        if (cm != 0) {
            atomicAdd(&g_lipsum[tid], sm);
            atomicAdd(&g_lipcnt[tid], cm);
        }
    }
}

// ---------------- kernel B: coalesced ballot scan -> kept list + S ----------------
__global__ __launch_bounds__(1024) void kScan(int T) {
    __shared__ int wtot[32];
    __shared__ int woff[32];

    int tid = threadIdx.x, lane = tid & 31, w = tid >> 5;
    int chunk = ((T + 1023) >> 10) << 5;      // contiguous ints per warp (mult of 32)
    int beg = w * chunk;
    int end = beg + chunk; if (end > T) end = T; if (beg > T) beg = T;

    // pass 1: count (coalesced)
    int cnt = 0;
    for (int b = beg; b < end; b += 32) {
        int idx = b + lane;
        int fl = (idx < end) ? g_keep[idx] : 0;
        unsigned bal = __ballot_sync(0xffffffffu, fl != 0);
        cnt += __popc(bal);
    }
    if (lane == 0) wtot[w] = cnt;
    __syncthreads();

    if (w == 0) {
        int v = wtot[lane];
        int inc = v;
        #pragma unroll
        for (int o = 1; o < 32; o <<= 1) {
            int n = __shfl_up_sync(0xffffffffu, inc, o);
            if (lane >= o) inc += n;
        }
        woff[lane] = inc - v;                 // exclusive
        if (lane == 31) g_S = inc;            // total
    }
    __syncthreads();

    // pass 2: emit (coalesced reads, compact writes)
    int off = woff[w];
    for (int b = beg; b < end; b += 32) {
        int idx = b + lane;
        int fl = (idx < end) ? g_keep[idx] : 0;
        unsigned bal = __ballot_sync(0xffffffffu, fl != 0);
        int pre = __popc(bal & ((1u << lane) - 1u));
        if (fl) g_kept[off + pre] = idx;
        off += __popc(bal);
    }
}

// ---------------- kernel C: segment means (one block / segment, split halves) ----------------
__global__ __launch_bounds__(256) void kC() {
    __shared__ int   s_idx[96];
    __shared__ float s_part[128];

    int seg = blockIdx.x;
    int tid = threadIdx.x;
    int half = tid >> 7;
    int p = tid & 127;

    int S = g_S;
    long long D = (S > 0) ? (long long)(S - 1) : 0LL;
    int start = (int)(((long long)seg * D) >> 9);
    int end   = (int)(((long long)(seg + 1) * D) >> 9);
    int n = end - start;

    for (int r = tid; r < n; r += 256) s_idx[r] = g_kept[start + r];
    __syncthreads();

    float total = 0.0f;
    if (p < NVAL) {
        float m = 0.0f;
        bool is_lip = (p >= 42);
        if (is_lip) {
            int c = g_lipcnt[p - 42];
            m = (c > 0) ? (g_lipsum[p - 42] / (float)c) : 0.0f;
        }
        float s0 = 0.f, s1 = 0.f, s2 = 0.f, s3 = 0.f;
        int r = half;                      // half 0: even rows, half 1: odd rows
        for (; r + 6 < n; r += 8) {
            float v0 = g_raw[(size_t)s_idx[r + 0] * ROWPAD + p];
            float v1 = g_raw[(size_t)s_idx[r + 2] * ROWPAD + p];
            float v2 = g_raw[(size_t)s_idx[r + 4] * ROWPAD + p];
            float v3 = g_raw[(size_t)s_idx[r + 6] * ROWPAD + p];
            if (is_lip) {
                if (isnan(v0)) v0 = m;
                if (isnan(v1)) v1 = m;
                if (isnan(v2)) v2 = m;
                if (isnan(v3)) v3 = m;
            }
            s0 += v0; s1 += v1; s2 += v2; s3 += v3;
        }
        for (; r < n; r += 2) {
            float v = g_raw[(size_t)s_idx[r] * ROWPAD + p];
            if (is_lip && isnan(v)) v = m;
            s0 += v;
        }
        total = (s0 + s1) + (s2 + s3);
    }
    if (half == 1) s_part[p] = total;
    __syncthreads();
    if (half == 0 && p < NVAL) {
        float t2 = total + s_part[p];
        g_sampled[seg * NVAL + p] = (n > 0) ? t2 / (float)n : 0.0f;
    }
}

// ---------------- kernel D: nonzero-row compaction into d_out ----------------
__global__ __launch_bounds__(512) void kD(float* __restrict__ out) {
    __shared__ int flg[NSEG];
    __shared__ int pos[NSEG];
    __shared__ int ws[32];

    int tid = threadIdx.x;
    float s = 0.0f;
    for (int c = 0; c < NVAL; c++) s += g_sampled[tid * NVAL + c];
    int f = (s != 0.0f) ? 1 : 0;

    int lane = tid & 31, w = tid >> 5;
    int v = f;
    #pragma unroll
    for (int o = 1; o < 32; o <<= 1) {
        int n = __shfl_up_sync(0xffffffffu, v, o);
        if (lane >= o) v += n;
    }
    if (lane == 31) ws[w] = v;
    __syncthreads();
    if (w == 0) {
        int x = (lane < 16) ? ws[lane] : 0;
        #pragma unroll
        for (int o = 1; o < 32; o <<= 1) {
            int n = __shfl_up_sync(0xffffffffu, x, o);
            if (lane >= o) x += n;
        }
        if (lane < 16) ws[lane] = x;
    }
    __syncthreads();
    int excl = v - f + (w > 0 ? ws[w - 1] : 0);
    flg[tid] = f;
    pos[tid] = excl;
    __syncthreads();

    for (int e = tid; e < NSEG * NVAL; e += 512) {
        int row = e / NVAL;
        int col = e - row * NVAL;
        if (flg[row]) out[pos[row] * NVAL + col] = g_sampled[e];
    }
}

// ---------------- launch ----------------
extern "C" void kernel_launch(void* const* d_in, const int* in_sizes, int n_in,
                              void* d_out, int out_size) {
    const float* frames  = (const float*)d_in[0];
    const int*   lipsidx = (const int*)d_in[1];
    int T = in_sizes[0] / (543 * 3);
    if (T > T_MAX) T = T_MAX;

    kInit<<<1, 128>>>();
    int blocksA = (T + 32 * NF - 1) / (32 * NF);
    kA<<<blocksA, 1024>>>(frames, lipsidx, T);
    kScan<<<1, 1024>>>(T);
    kC<<<NSEG, 256>>>();
    kD<<<1, 512>>>((float*)d_out);
}

// round 5
// speedup vs baseline: 1.7213x; 1.1008x over previous
#include <cuda_runtime.h>
#include <cuda_fp16.h>
#include <cstdint>
#include <math.h>

// ---------------- scratch (static device globals; no allocation) ----------------
#define T_MAX 32768
#define NVAL 122              // 61 landmarks x 2 coords
#define ROWPAD 128            // halves per row (256 B)
#define NSEG 512
#define NF 4                  // frames per warp in kA
#define NBLK_A 256            // max kA blocks (T_MAX / (32*NF))

__device__ __half    g_raw[(size_t)T_MAX * ROWPAD];   // fp16 staging (8 MB)
__device__ unsigned  g_keepbits[T_MAX / 32];
__device__ int       g_kept[T_MAX];
__device__ float     g_psum[80 * NBLK_A];             // [slot][block]
__device__ float     g_pcnt[80 * NBLK_A];
__device__ float     g_lipmean[80];
__device__ int       g_S;
__device__ float     g_sampled[NSEG * NVAL];
__device__ float     g_rowsum[NSEG];

// ---------------- kernel A: gather + hand transform + keep bits + lips partials ----------------
__global__ __launch_bounds__(1024) void kA(const float* __restrict__ frames,
                                           const int* __restrict__ lips_idx,
                                           int T) {
    __shared__ int      s_idx[40];
    __shared__ float    s_red[32 * 80];
    __shared__ float    s_redc[32 * 80];
    __shared__ unsigned s_kp[128];

    int tid  = threadIdx.x;
    int warp = tid >> 5;
    int lane = tid & 31;

    if (tid < 40) s_idx[tid] = lips_idx[tid];
    __syncthreads();

    int i0 = s_idx[lane];
    int i1 = (lane < 8) ? s_idx[32 + lane] : 0;

    float ax0 = 0.f, ay0 = 0.f, ax1 = 0.f, ay1 = 0.f;
    float cx0 = 0.f, cy0 = 0.f, cx1 = 0.f, cy1 = 0.f;

    int base = (blockIdx.x * 32 + warp) * NF;

    #pragma unroll
    for (int j = 0; j < NF; j++) {
        int t = base + j;
        bool valid = (t < T);
        const float* f = frames + (size_t)(valid ? t : 0) * (543 * 3);

        // --- issue ALL loads up front (independent, predicated not branched) ---
        bool hl = valid && (lane < 21);
        float lx = 0.f, ly = 0.f, rx = 0.f, ry = 0.f;
        if (hl) {
            lx = f[(468 + lane) * 3 + 0];
            ly = f[(468 + lane) * 3 + 1];
            rx = f[(522 + lane) * 3 + 0];
            ry = f[(522 + lane) * 3 + 1];
        }
        float x0 = 0.f, y0 = 0.f, x1 = 0.f, y1 = 0.f;
        if (valid) { x0 = f[i0 * 3 + 0]; y0 = f[i0 * 3 + 1]; }
        if (valid && lane < 8) { x1 = f[i1 * 3 + 0]; y1 = f[i1 * 3 + 1]; }

        // --- hand transform + keep flag ---
        float h0 = 0.f, h1 = 0.f;
        if (hl) {
            h0 = (isnan(lx) ? 0.f : lx)          + (isnan(rx) ? 0.f : (1.f - rx));
            h1 = (isnan(ly) ? 0.f : (1.f - ly))  + (isnan(ry) ? 0.f : (1.f - ry));
        }
        float s = h0 + h1;
        #pragma unroll
        for (int o = 16; o > 0; o >>= 1) s += __shfl_xor_sync(0xffffffffu, s, o);
        int kp = (s != 0.0f) ? 1 : 0;
        if (lane == 0) s_kp[warp * NF + j] = (unsigned)kp;

        if (valid) {
            __half* row = g_raw + (size_t)t * ROWPAD;
            if (lane < 21)
                *reinterpret_cast<__half2*>(row + 2 * lane) = __floats2half2_rn(h0, h1);
            *reinterpret_cast<__half2*>(row + 42 + 2 * lane) = __floats2half2_rn(x0, y0);
            if (lane < 8)
                *reinterpret_cast<__half2*>(row + 106 + 2 * lane) = __floats2half2_rn(x1, y1);

            if (kp) {
                if (!isnan(x0)) { ax0 += x0; cx0 += 1.f; }
                if (!isnan(y0)) { ay0 += y0; cy0 += 1.f; }
                if (lane < 8) {
                    if (!isnan(x1)) { ax1 += x1; cx1 += 1.f; }
                    if (!isnan(y1)) { ay1 += y1; cy1 += 1.f; }
                }
            }
        }
    }

    // --- per-warp partials -> shared ---
    s_red [warp * 80 + 2 * lane]     = ax0;
    s_red [warp * 80 + 2 * lane + 1] = ay0;
    s_redc[warp * 80 + 2 * lane]     = cx0;
    s_redc[warp * 80 + 2 * lane + 1] = cy0;
    if (lane < 8) {
        s_red [warp * 80 + 64 + 2 * lane]     = ax1;
        s_red [warp * 80 + 64 + 2 * lane + 1] = ay1;
        s_redc[warp * 80 + 64 + 2 * lane]     = cx1;
        s_redc[warp * 80 + 64 + 2 * lane + 1] = cy1;
    }
    __syncthreads();

    // keep bits: 128 frames/block -> 4 words via ballot (warps 0..3)
    if (tid < 128) {
        unsigned fl = s_kp[tid];
        unsigned bal = __ballot_sync(0xffffffffu, fl != 0u);
        if ((tid & 31) == 0) g_keepbits[blockIdx.x * 4 + (tid >> 5)] = bal;
    }

    // block reduce of lips partials -> global per-block slot (no atomics)
    if (tid < 80) {
        float sm = 0.f, cm = 0.f;
        #pragma unroll
        for (int w = 0; w < 32; w++) {
            sm += s_red [w * 80 + tid];
            cm += s_redc[w * 80 + tid];
        }
        g_psum[tid * NBLK_A + blockIdx.x] = sm;
        g_pcnt[tid * NBLK_A + blockIdx.x] = cm;
    }
}

// ---------------- kernel B: lip means + bitmask scan -> kept list + S ----------------
__global__ __launch_bounds__(1024) void kScan(int T, int nblk) {
    __shared__ int wtot[32];
    __shared__ int wexc[32];

    int tid = threadIdx.x, lane = tid & 31, w = tid >> 5;

    // part 1: reduce lips partials (warp per slot, coalesced)
    for (int s = w; s < 80; s += 32) {
        float sm = 0.f, cm = 0.f;
        for (int i = lane; i < nblk; i += 32) {
            sm += g_psum[s * NBLK_A + i];
            cm += g_pcnt[s * NBLK_A + i];
        }
        #pragma unroll
        for (int o = 16; o > 0; o >>= 1) {
            sm += __shfl_xor_sync(0xffffffffu, sm, o);
            cm += __shfl_xor_sync(0xffffffffu, cm, o);
        }
        if (lane == 0) g_lipmean[s] = (cm > 0.f) ? (sm / cm) : 0.f;
    }

    // part 2: one keep-word per thread
    int nwords = (T + 31) >> 5;
    unsigned word = (tid < nwords) ? g_keepbits[tid] : 0u;
    int c = __popc(word);

    int v = c;
    #pragma unroll
    for (int o = 1; o < 32; o <<= 1) {
        int n = __shfl_up_sync(0xffffffffu, v, o);
        if (lane >= o) v += n;
    }
    if (lane == 31) wtot[w] = v;
    __syncthreads();
    if (w == 0) {
        int x = wtot[lane];
        int inc = x;
        #pragma unroll
        for (int o = 1; o < 32; o <<= 1) {
            int n = __shfl_up_sync(0xffffffffu, inc, o);
            if (lane >= o) inc += n;
        }
        wexc[lane] = inc - x;
        if (lane == 31) g_S = inc;
    }
    __syncthreads();

    int off = (v - c) + wexc[w];
    int fb = tid << 5;
    while (word) {
        int b = __ffs(word) - 1;
        g_kept[off++] = fb + b;
        word &= (word - 1u);
    }
}

// ---------------- kernel C: segment means + row sums ----------------
__global__ __launch_bounds__(256) void kC() {
    __shared__ int   s_idx[96];
    __shared__ float s_part[128];
    __shared__ float s_val[128];

    int seg = blockIdx.x;
    int tid = threadIdx.x;
    int half = tid >> 7;
    int p = tid & 127;

    int S = g_S;
    long long D = (S > 0) ? (long long)(S - 1) : 0LL;
    int start = (int)(((long long)seg * D) >> 9);
    int end   = (int)(((long long)(seg + 1) * D) >> 9);
    int n = end - start;

    for (int r = tid; r < n; r += 256) s_idx[r] = g_kept[start + r];
    __syncthreads();

    float total = 0.0f;
    if (p < NVAL) {
        bool is_lip = (p >= 42);
        float m = is_lip ? g_lipmean[p - 42] : 0.0f;

        float s0 = 0.f, s1 = 0.f, s2 = 0.f, s3 = 0.f;
        int r = half;                      // half 0: even rows, half 1: odd rows
        for (; r + 6 < n; r += 8) {
            float v0 = __half2float(g_raw[(size_t)s_idx[r + 0] * ROWPAD + p]);
            float v1 = __half2float(g_raw[(size_t)s_idx[r + 2] * ROWPAD + p]);
            float v2 = __half2float(g_raw[(size_t)s_idx[r + 4] * ROWPAD + p]);
            float v3 = __half2float(g_raw[(size_t)s_idx[r + 6] * ROWPAD + p]);
            if (is_lip) {
                if (isnan(v0)) v0 = m;
                if (isnan(v1)) v1 = m;
                if (isnan(v2)) v2 = m;
                if (isnan(v3)) v3 = m;
            }
            s0 += v0; s1 += v1; s2 += v2; s3 += v3;
        }
        for (; r < n; r += 2) {
            float v = __half2float(g_raw[(size_t)s_idx[r] * ROWPAD + p]);
            if (is_lip && isnan(v)) v = m;
            s0 += v;
        }
        total = (s0 + s1) + (s2 + s3);
    }
    if (half == 1) s_part[p] = total;
    __syncthreads();

    float mean = 0.0f;
    if (half == 0) {
        if (p < NVAL) {
            mean = (n > 0) ? (total + s_part[p]) / (float)n : 0.0f;
            g_sampled[seg * NVAL + p] = mean;
        }
        s_val[p] = mean;   // 0 for p >= NVAL
    }
    __syncthreads();

    if (tid < 32) {
        float t = s_val[tid] + s_val[tid + 32] + s_val[tid + 64] + s_val[tid + 96];
        #pragma unroll
        for (int o = 16; o > 0; o >>= 1) t += __shfl_xor_sync(0xffffffffu, t, o);
        if (tid == 0) g_rowsum[seg] = t;
    }
}

// ---------------- kernel D: flag scan + coalesced compaction copy ----------------
__global__ __launch_bounds__(1024) void kD(float* __restrict__ out) {
    __shared__ int flg[NSEG];
    __shared__ int pos[NSEG];
    __shared__ int wtot[32];
    __shared__ int wexc[32];

    int tid = threadIdx.x, lane = tid & 31, w = tid >> 5;

    int f = 0;
    if (tid < NSEG) f = (g_rowsum[tid] != 0.0f) ? 1 : 0;

    int v = f;
    #pragma unroll
    for (int o = 1; o < 32; o <<= 1) {
        int n = __shfl_up_sync(0xffffffffu, v, o);
        if (lane >= o) v += n;
    }
    if (lane == 31) wtot[w] = v;
    __syncthreads();
    if (w == 0) {
        int x = wtot[lane];
        int inc = x;
        #pragma unroll
        for (int o = 1; o < 32; o <<= 1) {
            int n = __shfl_up_sync(0xffffffffu, inc, o);
            if (lane >= o) inc += n;
        }
        wexc[lane] = inc - x;
    }
    __syncthreads();

    if (tid < NSEG) {
        flg[tid] = f;
        pos[tid] = (v - f) + wexc[w];
    }
    __syncthreads();

    for (int e = tid; e < NSEG * NVAL; e += 1024) {
        int row = e / NVAL;
        int col = e - row * NVAL;
        if (flg[row]) out[pos[row] * NVAL + col] = g_sampled[e];
    }
}

// ---------------- launch ----------------
extern "C" void kernel_launch(void* const* d_in, const int* in_sizes, int n_in,
                              void* d_out, int out_size) {
    const float* frames  = (const float*)d_in[0];
    const int*   lipsidx = (const int*)d_in[1];
    int T = in_sizes[0] / (543 * 3);
    if (T > T_MAX) T = T_MAX;

    int blocksA = (T + 32 * NF - 1) / (32 * NF);
    kA<<<blocksA, 1024>>>(frames, lipsidx, T);
    kScan<<<1, 1024>>>(T, blocksA);
    kC<<<NSEG, 256>>>();
    kD<<<1, 1024>>>((float*)d_out);
}

// round 6
// speedup vs baseline: 2.0973x; 1.2185x over previous
#include <cuda_runtime.h>
#include <cuda_fp16.h>
#include <cstdint>
#include <math.h>

// ---------------- scratch (static device globals; no allocation) ----------------
#define T_MAX 32768
#define NVAL 122              // 61 landmarks x 2 coords
#define ROWPAD 128            // halves per row (256 B)
#define NSEG 512
#define NF 4                  // frames per warp in kA
#define NBLK_A 256            // max kA blocks (T_MAX / (32*NF))

__device__ __half    g_raw[(size_t)T_MAX * ROWPAD];   // fp16 staging (8 MB)
__device__ unsigned  g_keepbits[T_MAX / 32];
__device__ int       g_kept[T_MAX];
__device__ float     g_psum[80 * NBLK_A];             // [slot][block]
__device__ float     g_pcnt[80 * NBLK_A];
__device__ float     g_lipmean[80];
__device__ int       g_S;
__device__ float     g_sampled[NSEG * NVAL];
__device__ float     g_rowsum[NSEG];

// ---------------- kernel A: gather + hand transform + keep bits + lips partials ----------------
// Phase 1: front-batch ALL loads for NF frames (max MLP); Phase 2: compute + store.
__global__ __launch_bounds__(1024) void kA(const float* __restrict__ frames,
                                           const int* __restrict__ lips_idx,
                                           int T) {
    __shared__ int      s_idx[40];
    __shared__ float    s_red[32 * 80];
    __shared__ float    s_redc[32 * 80];
    __shared__ unsigned s_kp[128];

    int tid  = threadIdx.x;
    int warp = tid >> 5;
    int lane = tid & 31;

    if (tid < 40) s_idx[tid] = lips_idx[tid];
    __syncthreads();

    int i0 = s_idx[lane];
    int i1 = (lane < 8) ? s_idx[32 + lane] : 0;

    int base = (blockIdx.x * 32 + warp) * NF;
    bool hl = (lane < 21);
    bool l8 = (lane < 8);

    float lx[NF], ly[NF], rx[NF], ry[NF];
    float x0[NF], y0[NF], x1[NF], y1[NF];

    // ---- phase 1: issue every load, no sync points in between ----
    #pragma unroll
    for (int j = 0; j < NF; j++) {
        int t = base + j;
        bool valid = (t < T);
        const float* f = frames + (size_t)(valid ? t : 0) * (543 * 3);
        lx[j] = ly[j] = rx[j] = ry[j] = 0.f;
        x0[j] = y0[j] = x1[j] = y1[j] = 0.f;
        if (valid && hl) {
            lx[j] = f[(468 + lane) * 3 + 0];
            ly[j] = f[(468 + lane) * 3 + 1];
            rx[j] = f[(522 + lane) * 3 + 0];
            ry[j] = f[(522 + lane) * 3 + 1];
        }
        if (valid) { x0[j] = f[i0 * 3 + 0]; y0[j] = f[i0 * 3 + 1]; }
        if (valid && l8) { x1[j] = f[i1 * 3 + 0]; y1[j] = f[i1 * 3 + 1]; }
    }

    // ---- phase 2: compute, reduce, store ----
    float ax0 = 0.f, ay0 = 0.f, ax1 = 0.f, ay1 = 0.f;
    float cx0 = 0.f, cy0 = 0.f, cx1 = 0.f, cy1 = 0.f;

    #pragma unroll
    for (int j = 0; j < NF; j++) {
        int t = base + j;
        bool valid = (t < T);

        float h0 = 0.f, h1 = 0.f;
        if (hl) {
            h0 = (isnan(lx[j]) ? 0.f : lx[j])         + (isnan(rx[j]) ? 0.f : (1.f - rx[j]));
            h1 = (isnan(ly[j]) ? 0.f : (1.f - ly[j])) + (isnan(ry[j]) ? 0.f : (1.f - ry[j]));
        }
        float s = h0 + h1;
        #pragma unroll
        for (int o = 16; o > 0; o >>= 1) s += __shfl_xor_sync(0xffffffffu, s, o);
        int kp = (s != 0.0f) ? 1 : 0;
        if (lane == 0) s_kp[warp * NF + j] = (unsigned)kp;

        if (valid) {
            __half* row = g_raw + (size_t)t * ROWPAD;
            if (hl)
                *reinterpret_cast<__half2*>(row + 2 * lane) = __floats2half2_rn(h0, h1);
            *reinterpret_cast<__half2*>(row + 42 + 2 * lane) = __floats2half2_rn(x0[j], y0[j]);
            if (l8)
                *reinterpret_cast<__half2*>(row + 106 + 2 * lane) = __floats2half2_rn(x1[j], y1[j]);

            if (kp) {
                if (!isnan(x0[j])) { ax0 += x0[j]; cx0 += 1.f; }
                if (!isnan(y0[j])) { ay0 += y0[j]; cy0 += 1.f; }
                if (l8) {
                    if (!isnan(x1[j])) { ax1 += x1[j]; cx1 += 1.f; }
                    if (!isnan(y1[j])) { ay1 += y1[j]; cy1 += 1.f; }
                }
            }
        }
    }

    // --- per-warp partials -> shared ---
    s_red [warp * 80 + 2 * lane]     = ax0;
    s_red [warp * 80 + 2 * lane + 1] = ay0;
    s_redc[warp * 80 + 2 * lane]     = cx0;
    s_redc[warp * 80 + 2 * lane + 1] = cy0;
    if (l8) {
        s_red [warp * 80 + 64 + 2 * lane]     = ax1;
        s_red [warp * 80 + 64 + 2 * lane + 1] = ay1;
        s_redc[warp * 80 + 64 + 2 * lane]     = cx1;
        s_redc[warp * 80 + 64 + 2 * lane + 1] = cy1;
    }
    __syncthreads();

    // keep bits: 128 frames/block -> 4 words via ballot (warps 0..3)
    if (tid < 128) {
        unsigned fl = s_kp[tid];
        unsigned bal = __ballot_sync(0xffffffffu, fl != 0u);
        if ((tid & 31) == 0) g_keepbits[blockIdx.x * 4 + (tid >> 5)] = bal;
    }

    // block reduce of lips partials -> global per-block slot (no atomics)
    if (tid < 80) {
        float sm = 0.f, cm = 0.f;
        #pragma unroll
        for (int w = 0; w < 32; w++) {
            sm += s_red [w * 80 + tid];
            cm += s_redc[w * 80 + tid];
        }
        g_psum[tid * NBLK_A + blockIdx.x] = sm;
        g_pcnt[tid * NBLK_A + blockIdx.x] = cm;
    }
}

// ---------------- kernel B: lip means + bitmask scan -> kept list + S ----------------
__global__ __launch_bounds__(1024) void kScan(int T, int nblk) {
    __shared__ int wtot[32];
    __shared__ int wexc[32];

    int tid = threadIdx.x, lane = tid & 31, w = tid >> 5;

    // part 1: reduce lips partials (warp per slot, coalesced)
    for (int s = w; s < 80; s += 32) {
        float sm = 0.f, cm = 0.f;
        for (int i = lane; i < nblk; i += 32) {
            sm += g_psum[s * NBLK_A + i];
            cm += g_pcnt[s * NBLK_A + i];
        }
        #pragma unroll
        for (int o = 16; o > 0; o >>= 1) {
            sm += __shfl_xor_sync(0xffffffffu, sm, o);
            cm += __shfl_xor_sync(0xffffffffu, cm, o);
        }
        if (lane == 0) g_lipmean[s] = (cm > 0.f) ? (sm / cm) : 0.f;
    }

    // part 2: one keep-word per thread
    int nwords = (T + 31) >> 5;
    unsigned word = (tid < nwords) ? g_keepbits[tid] : 0u;
    int c = __popc(word);

    int v = c;
    #pragma unroll
    for (int o = 1; o < 32; o <<= 1) {
        int n = __shfl_up_sync(0xffffffffu, v, o);
        if (lane >= o) v += n;
    }
    if (lane == 31) wtot[w] = v;
    __syncthreads();
    if (w == 0) {
        int x = wtot[lane];
        int inc = x;
        #pragma unroll
        for (int o = 1; o < 32; o <<= 1) {
            int n = __shfl_up_sync(0xffffffffu, inc, o);
            if (lane >= o) inc += n;
        }
        wexc[lane] = inc - x;
        if (lane == 31) g_S = inc;
    }
    __syncthreads();

    int off = (v - c) + wexc[w];
    int fb = tid << 5;
    while (word) {
        int b = __ffs(word) - 1;
        g_kept[off++] = fb + b;
        word &= (word - 1u);
    }
}

// ---------------- kernel C: segment means + row sums ----------------
__global__ __launch_bounds__(256) void kC() {
    __shared__ int   s_idx[96];
    __shared__ float s_part[128];
    __shared__ float s_val[128];

    int seg = blockIdx.x;
    int tid = threadIdx.x;
    int half = tid >> 7;
    int p = tid & 127;

    int S = g_S;
    long long D = (S > 0) ? (long long)(S - 1) : 0LL;
    int start = (int)(((long long)seg * D) >> 9);
    int end   = (int)(((long long)(seg + 1) * D) >> 9);
    int n = end - start;

    for (int r = tid; r < n; r += 256) s_idx[r] = g_kept[start + r];
    __syncthreads();

    float total = 0.0f;
    if (p < NVAL) {
        bool is_lip = (p >= 42);
        float m = is_lip ? g_lipmean[p - 42] : 0.0f;

        float s0 = 0.f, s1 = 0.f, s2 = 0.f, s3 = 0.f;
        int r = half;                      // half 0: even rows, half 1: odd rows
        for (; r + 6 < n; r += 8) {
            float v0 = __half2float(g_raw[(size_t)s_idx[r + 0] * ROWPAD + p]);
            float v1 = __half2float(g_raw[(size_t)s_idx[r + 2] * ROWPAD + p]);
            float v2 = __half2float(g_raw[(size_t)s_idx[r + 4] * ROWPAD + p]);
            float v3 = __half2float(g_raw[(size_t)s_idx[r + 6] * ROWPAD + p]);
            if (is_lip) {
                if (isnan(v0)) v0 = m;
                if (isnan(v1)) v1 = m;
                if (isnan(v2)) v2 = m;
                if (isnan(v3)) v3 = m;
            }
            s0 += v0; s1 += v1; s2 += v2; s3 += v3;
        }
        for (; r < n; r += 2) {
            float v = __half2float(g_raw[(size_t)s_idx[r] * ROWPAD + p]);
            if (is_lip && isnan(v)) v = m;
            s0 += v;
        }
        total = (s0 + s1) + (s2 + s3);
    }
    if (half == 1) s_part[p] = total;
    __syncthreads();

    float mean = 0.0f;
    if (half == 0) {
        if (p < NVAL) {
            mean = (n > 0) ? (total + s_part[p]) / (float)n : 0.0f;
            g_sampled[seg * NVAL + p] = mean;
        }
        s_val[p] = mean;   // 0 for p >= NVAL
    }
    __syncthreads();

    if (tid < 32) {
        float t = s_val[tid] + s_val[tid + 32] + s_val[tid + 64] + s_val[tid + 96];
        #pragma unroll
        for (int o = 16; o > 0; o >>= 1) t += __shfl_xor_sync(0xffffffffu, t, o);
        if (tid == 0) g_rowsum[seg] = t;
    }
}

// ---------------- kernel D: distributed compaction copy ----------------
// Every block redoes the tiny 512-flag scan (2 KB read), then copies its own
// coalesced 1024-element slice. 60 blocks -> spreads LSU work across SMs.
__global__ __launch_bounds__(1024) void kD(float* __restrict__ out) {
    __shared__ int flg[NSEG];
    __shared__ int pos[NSEG];
    __shared__ int wtot[16];
    __shared__ int wexc[16];

    int tid = threadIdx.x, lane = tid & 31, w = tid >> 5;

    int f = 0, v = 0;
    if (tid < NSEG) {
        f = (g_rowsum[tid] != 0.0f) ? 1 : 0;
        v = f;
        #pragma unroll
        for (int o = 1; o < 32; o <<= 1) {
            int n = __shfl_up_sync(0xffffffffu, v, o);
            if (lane >= o) v += n;
        }
        if (lane == 31) wtot[w] = v;
    }
    __syncthreads();
    if (w == 0 && lane < 16) {
        int x = wtot[lane];
        int inc = x;
        #pragma unroll
        for (int o = 1; o < 16; o <<= 1) {
            int n = __shfl_up_sync(0x0000ffffu, inc, o);
            if (lane >= o) inc += n;
        }
        wexc[lane] = inc - x;
    }
    __syncthreads();

    if (tid < NSEG) {
        flg[tid] = f;
        pos[tid] = (v - f) + wexc[w];
    }
    __syncthreads();

    int e = blockIdx.x * 1024 + tid;
    if (e < NSEG * NVAL) {
        int row = e / NVAL;
        int col = e - row * NVAL;
        if (flg[row]) out[pos[row] * NVAL + col] = g_sampled[e];
    }
}

// ---------------- launch ----------------
extern "C" void kernel_launch(void* const* d_in, const int* in_sizes, int n_in,
                              void* d_out, int out_size) {
    const float* frames  = (const float*)d_in[0];
    const int*   lipsidx = (const int*)d_in[1];
    int T = in_sizes[0] / (543 * 3);
    if (T > T_MAX) T = T_MAX;

    int blocksA = (T + 32 * NF - 1) / (32 * NF);
    kA<<<blocksA, 1024>>>(frames, lipsidx, T);
    kScan<<<1, 1024>>>(T, blocksA);
    kC<<<NSEG, 256>>>();
    int blocksD = (NSEG * NVAL + 1023) / 1024;
    kD<<<blocksD, 1024>>>((float*)d_out);
}